// round 11
// baseline (speedup 1.0000x reference)
#include <cuda_runtime.h>
#include <math.h>

#define T_STEPS 2048
#define BATCH   64
#define IN_DIM  27
#define H1      400
#define H2      200
#define GRID_R  148          // 104 x 3 units + 44 x 2 units = 400
#define K4      (H1 / 4)
#define KW      428          // 400 h + 27 x + 1 pad
#define KW4     107          // quads: 100 h + 7 x(incl pad)

// ---------------- device scratch (static; zero-init) ----------------
// g_hr [t][k>>2][b][k&3]; slot t=0 is h_{-1}=0 (never written)
static __device__ float g_hr[(size_t)(T_STEPS + 1) * H1 * BATCH];
static __device__ unsigned int g_bar;

__device__ __forceinline__ void ffma2(unsigned long long &acc,
                                      unsigned long long a, unsigned long long b) {
    asm("fma.rn.f32x2 %0, %1, %2, %0;" : "+l"(acc) : "l"(a), "l"(b));
}
__device__ __forceinline__ float lo32(unsigned long long v) { return __uint_as_float((unsigned)v); }
__device__ __forceinline__ float hi32(unsigned long long v) { return __uint_as_float((unsigned)(v >> 32)); }

// =====================================================================
// Kernel 1: persistent recurrence (input projection fused).
// grid 148, block 256, 1 CTA/SM. R4 mapping: warp = (ks 0..3, bg 0..1),
// thread: R rows x 1 batch over its k-range of the 428-wide concat input.
// static smem: ws[R<=12][428] | xs[2][7*256] | pr[4][R][64]
// =====================================================================
template<int NU>
__device__ __forceinline__ void rec_body(const float* __restrict__ Whh,
                                         const float* __restrict__ Wih,
                                         const float* __restrict__ bih,
                                         const float* __restrict__ bhh,
                                         const float* __restrict__ word,
                                         int u0, float* ws, float* xs, float* pr) {
    constexpr int R = 4 * NU;
    const int tid  = threadIdx.x;
    const int lane = tid & 31;
    const int wid  = tid >> 5;
    const int ks   = wid & 3;                // k-split 0..3
    const int bg   = wid >> 2;               // batch group 0..1
    const int b    = bg * 32 + lane;

    // ---- stage combined weights ws[lr][428] = [W_hh row | W_ih row | 0]
    for (int idx = tid; idx < R * KW; idx += 256) {
        int lr = idx / KW, k = idx - lr * KW;
        int gate = lr / NU, q = lr - gate * NU;
        int grow = gate * H1 + u0 + q;
        float w;
        if (k < H1)            w = Whh[(size_t)grow * H1 + k];
        else if (k < H1 + IN_DIM) w = Wih[(size_t)grow * IN_DIM + (k - H1)];
        else                   w = 0.0f;
        ws[lr * KW + k] = w;
    }
    // zero both x buffers (covers the k=427 pad slot permanently)
    for (int i = tid; i < 2 * 7 * 256; i += 256) xs[i] = 0.0f;

    // combine mapping
    const int cb = tid & 63;
    const int q  = tid >> 6;
    const int uu = u0 + (q < NU ? q : NU - 1);
    const size_t hr_off = (size_t)(uu >> 2) * 256 + cb * 4 + (uu & 3);
    float c_val = 0.0f;

    // per-thread gate biases (b_ih + b_hh), loaded once
    float bs0 = 0.f, bs1 = 0.f, bs2 = 0.f, bs3 = 0.f;
    if (q < NU) {
        bs0 = bih[0 * H1 + uu] + bhh[0 * H1 + uu];
        bs1 = bih[1 * H1 + uu] + bhh[1 * H1 + uu];
        bs2 = bih[2 * H1 + uu] + bhh[2 * H1 + uu];
        bs3 = bih[3 * H1 + uu] + bhh[3 * H1 + uu];
    }
    __syncthreads();

    // ---- stage x[0] into buffer 0 (transpose [b][i] -> [i>>2][b][i&3]) ----
    #pragma unroll
    for (int i = 0; i < 7; i++) {
        int e = tid + i * 256;
        if (e < BATCH * IN_DIM) {
            int bb = e / IN_DIM, ii = e - bb * IN_DIM;
            xs[(ii >> 2) * 256 + bb * 4 + (ii & 3)] = __ldg(&word[e]);
        }
    }
    __syncthreads();

    const int k4lo = ks * 27;                    // 0,27,54,81
    const int nh   = (ks < 3) ? 27 : 19;         // h-quads this warp

    for (int t = 0; t < T_STEPS; t++) {
        float* xcur = xs + (t & 1) * (7 * 256);

        // ---- dots over h-part (direct L2 loads, 1-deep prefetch) ----
        unsigned long long acc[R];
        #pragma unroll
        for (int lr = 0; lr < R; lr++) acc[lr] = 0ull;

        const float* hbase = g_hr + (size_t)t * (H1 * BATCH);
        ulonglong2 h_cur = __ldcg((const ulonglong2*)(hbase + k4lo * 256 + b * 4));
        #pragma unroll 4
        for (int i = 0; i < nh; i++) {
            ulonglong2 h4 = h_cur;
            if (i + 1 < nh)
                h_cur = __ldcg((const ulonglong2*)(hbase + (k4lo + i + 1) * 256 + b * 4));
            const int k4 = k4lo + i;
            #pragma unroll
            for (int lr = 0; lr < R; lr++) {
                ulonglong2 w2 = *(const ulonglong2*)&ws[lr * KW + k4 * 4];
                ffma2(acc[lr], h4.x, w2.x);
                ffma2(acc[lr], h4.y, w2.y);
            }
        }
        // ---- x-part (ks==3 only): quads 100..106 from smem ----
        if (ks == 3) {
            #pragma unroll
            for (int j = 0; j < 7; j++) {
                ulonglong2 h4 = *(const ulonglong2*)&xcur[j * 256 + b * 4];
                const int k4 = 100 + j;
                #pragma unroll
                for (int lr = 0; lr < R; lr++) {
                    ulonglong2 w2 = *(const ulonglong2*)&ws[lr * KW + k4 * 4];
                    ffma2(acc[lr], h4.x, w2.x);
                    ffma2(acc[lr], h4.y, w2.y);
                }
            }
        }
        #pragma unroll
        for (int lr = 0; lr < R; lr++)
            pr[(ks * R + lr) * 64 + b] = lo32(acc[lr]) + hi32(acc[lr]);
        __syncthreads();

        // ---- combine: LSTM cell for (unit uu, batch cb) ----
        if (q < NU) {
            float g0 = bs0, g1 = bs1, g2 = bs2, g3 = bs3;
            #pragma unroll
            for (int s = 0; s < 4; s++) {
                g0 += pr[(s * R + 0 * NU + q) * 64 + cb];
                g1 += pr[(s * R + 1 * NU + q) * 64 + cb];
                g2 += pr[(s * R + 2 * NU + q) * 64 + cb];
                g3 += pr[(s * R + 3 * NU + q) * 64 + cb];
            }
            float iv = 1.0f / (1.0f + expf(-g0));
            float fv = 1.0f / (1.0f + expf(-g1));
            float gv = tanhf(g2);
            float ov = 1.0f / (1.0f + expf(-g3));
            float cn = fv * c_val + iv * gv;
            float hn = ov * tanhf(cn);
            c_val = fmaxf(cn, 0.0f);
            g_hr[(size_t)(t + 1) * (H1 * BATCH) + hr_off] = fmaxf(hn, 0.0f);
        }

        // ---- stage x[t+1] into the other buffer (pure input, no deps) ----
        if (t + 1 < T_STEPS) {
            float* xnxt = xs + ((t + 1) & 1) * (7 * 256);
            const float* wsrc = word + (size_t)(t + 1) * (BATCH * IN_DIM);
            #pragma unroll
            for (int i = 0; i < 7; i++) {
                int e = tid + i * 256;
                if (e < BATCH * IN_DIM) {
                    int bb = e / IN_DIM, ii = e - bb * IN_DIM;
                    xnxt[(ii >> 2) * 256 + bb * 4 + (ii & 3)] = __ldg(&wsrc[e]);
                }
            }
        }

        // ---- grid barrier: sync, tid0 fence+arrive+poll, sync ----
        __syncthreads();
        if (tid == 0) {
            __threadfence();
            atomicAdd(&g_bar, 1u);
            const unsigned target = (unsigned)(t + 1) * GRID_R;
            unsigned v;
            do {
                asm volatile("ld.acquire.gpu.u32 %0, [%1];" : "=r"(v) : "l"(&g_bar));
            } while (v < target);
        }
        __syncthreads();
    }
}

__global__ void __launch_bounds__(256, 1) k_rec(const float* __restrict__ Whh,
                                                const float* __restrict__ Wih,
                                                const float* __restrict__ bih,
                                                const float* __restrict__ bhh,
                                                const float* __restrict__ word) {
    __shared__ float ws[12 * KW];        // 5136 f
    __shared__ float xs[2 * 7 * 256];    // 3584 f
    __shared__ float pr[4 * 12 * 64];    // 3072 f  -> total ~46KB static
    const int bid = blockIdx.x;
    if (bid < 104) rec_body<3>(Whh, Wih, bih, bhh, word, bid * 3, ws, xs, pr);
    else           rec_body<2>(Whh, Wih, bih, bhh, word, 312 + (bid - 104) * 2, ws, xs, pr);
}

// =====================================================================
// Kernel 2: MLP head per timestep. grid 2048, block 256.
// Also resets the grid-barrier counter for the next replay.
// =====================================================================
#define HS_F 25600
#define HEAD_SMEM_B ((HS_F + H2 * BATCH) * 4)

__global__ void __launch_bounds__(256) k_head(const float* __restrict__ Wfc,
                                              const float* __restrict__ bfc,
                                              const float* __restrict__ Wout,
                                              const float* __restrict__ bout,
                                              float* __restrict__ out) {
    extern __shared__ float sm[];
    float* hs  = sm;
    float* hid = sm + HS_F;
    const int t = blockIdx.x;
    const int tid = threadIdx.x;

    if (blockIdx.x == 0 && tid == 0) g_bar = 0u;   // reset for next replay

    const float4* hsrc = (const float4*)(g_hr + (size_t)(t + 1) * (H1 * BATCH));
    for (int i = tid; i < (H1 * BATCH) / 4; i += 256)
        ((float4*)hs)[i] = hsrc[i];
    __syncthreads();

    const int jrow = tid >> 4;
    const int bq   = (tid & 15) * 4;
    for (int j = jrow; j < H2; j += 16) {
        float bv = bfc[j];
        float4 acc = make_float4(bv, bv, bv, bv);
        const float4* wr = (const float4*)(Wfc + (size_t)j * H1);
        #pragma unroll 4
        for (int k4 = 0; k4 < K4; k4++) {
            float4 w4 = wr[k4];
            float4 h0 = *(const float4*)&hs[k4 * 256 + (bq + 0) * 4];
            float4 h1 = *(const float4*)&hs[k4 * 256 + (bq + 1) * 4];
            float4 h2 = *(const float4*)&hs[k4 * 256 + (bq + 2) * 4];
            float4 h3 = *(const float4*)&hs[k4 * 256 + (bq + 3) * 4];
            acc.x += w4.x * h0.x + w4.y * h0.y + w4.z * h0.z + w4.w * h0.w;
            acc.y += w4.x * h1.x + w4.y * h1.y + w4.z * h1.z + w4.w * h1.w;
            acc.z += w4.x * h2.x + w4.y * h2.y + w4.z * h2.z + w4.w * h2.w;
            acc.w += w4.x * h3.x + w4.y * h3.y + w4.z * h3.z + w4.w * h3.w;
        }
        acc.x = fmaxf(acc.x, 0.f); acc.y = fmaxf(acc.y, 0.f);
        acc.z = fmaxf(acc.z, 0.f); acc.w = fmaxf(acc.w, 0.f);
        *(float4*)&hid[j * BATCH + bq] = acc;
    }
    __syncthreads();

    if (tid < BATCH) {
        float s = bout[0];
        #pragma unroll 8
        for (int j = 0; j < H2; j++)
            s += hid[j * BATCH + tid] * Wout[j];
        out[(size_t)t * BATCH + tid] = 1.0f / (1.0f + expf(-s));
    }
}

// =====================================================================
extern "C" void kernel_launch(void* const* d_in, const int* in_sizes, int n_in,
                              void* d_out, int out_size) {
    const float* word = (const float*)d_in[0];
    const float* Wih  = (const float*)d_in[1];
    const float* Whh  = (const float*)d_in[2];
    const float* bih  = (const float*)d_in[3];
    const float* bhh  = (const float*)d_in[4];
    const float* Wfc  = (const float*)d_in[5];
    const float* bfc  = (const float*)d_in[6];
    const float* Wout = (const float*)d_in[7];
    const float* bout = (const float*)d_in[8];
    float* out = (float*)d_out;

    cudaFuncSetAttribute(k_head, cudaFuncAttributeMaxDynamicSharedMemorySize, HEAD_SMEM_B);

    k_rec<<<GRID_R, 256>>>(Whh, Wih, bih, bhh, word);
    k_head<<<T_STEPS, 256, HEAD_SMEM_B>>>(Wfc, bfc, Wout, bout, out);
}